// round 11
// baseline (speedup 1.0000x reference)
#include <cuda_runtime.h>
#include <cuda_bf16.h>
#include <mma.h>
#include <cstdint>

using namespace nvcuda;

#define N_NODES 100000
#define HIDDEN  128
#define N_EDGES 1600000

// GEMM tiling: persistent blocks, 16-row tiles, warp owns a 16-col slice.
#define TILE_ROWS 16
#define NTILES    (N_NODES / TILE_ROWS)            // 6250 (exact)
#define WLD       132                              // padded shared ld for W
#define GEMM_SMEM ((128 * WLD + 16 * HIDDEN) * 4)
#define GEMM_GRID 296                              // 2 blocks/SM

// scan config
#define SCAN_CHUNK   1024
#define NSCAN_BLOCKS ((N_NODES + SCAN_CHUNK - 1) / SCAN_CHUNK)   // 98

// ---------------- scratch (no allocations -> __device__ globals) ------------
__device__ float          g_S [(size_t)N_NODES * HIDDEN];
__device__ float          g_I [(size_t)N_NODES * HIDDEN];
__device__ __nv_bfloat16  g_Ibf[(size_t)N_NODES * HIDDEN];  // bf16 mirror of I
__device__ int   g_rows[N_EDGES];
__device__ int   g_cols[N_EDGES];
__device__ int   g_deg[N_NODES];
__device__ int   g_rowptr[N_NODES];
__device__ int   g_cursor[N_NODES];
__device__ int   g_edst[N_EDGES];
__device__ int   g_bsum[NSCAN_BLOCKS];
__device__ int   g_is64;

// bf16x2 <-> u32 bit reinterpretation helpers (no dedicated intrinsics in
// this toolkit's cuda_bf16.h; plain bit-casts are exact).
__device__ __forceinline__ unsigned bf2_to_u32(__nv_bfloat162 v) {
    return *reinterpret_cast<unsigned*>(&v);
}
__device__ __forceinline__ float2 u32_to_f2(unsigned u) {
    return __bfloat1622float2(*reinterpret_cast<__nv_bfloat162*>(&u));
}

// ---------------- index dtype probe ----------------------------------------
// int64 data: hi-words are 0 -> int64 view of first 512 entries all lie in
// [0, N_NODES). int32 data: the int64 view pairs two random indices -> the
// hi-word is itself a random index, essentially never 0 for all 512 samples.
// Deterministic for fixed input bytes -> graph/replay safe.
__global__ void detect_kernel(const void* rows) {
    const long long* p = (const long long*)rows;
    int ok64 = 1;
    for (int i = 0; i < 512; i++) {
        long long v = p[i];
        if (v < 0 || v >= N_NODES) { ok64 = 0; break; }
    }
    g_is64 = ok64;
}

__global__ void zero_deg_kernel() {
    int i = blockIdx.x * blockDim.x + threadIdx.x;
    if (i < N_NODES) g_deg[i] = 0;
}

// convert indices to int32 AND histogram the rows
__global__ void convert_hist_kernel(const void* __restrict__ rows,
                                    const void* __restrict__ cols) {
    int i = blockIdx.x * blockDim.x + threadIdx.x;
    if (i >= N_EDGES) return;
    int r, c;
    if (g_is64) {
        r = (int)((const long long*)rows)[i];
        c = (int)((const long long*)cols)[i];
    } else {
        r = ((const int*)rows)[i];
        c = ((const int*)cols)[i];
    }
    g_rows[i] = r;
    g_cols[i] = c;
    atomicAdd(&g_deg[r], 1);
}

// ---------------- exclusive scan of g_deg -> g_rowptr (3 kernels) -----------
__global__ void __launch_bounds__(256) scan1_kernel() {
    __shared__ int sums[256];
    int b = blockIdx.x, t = threadIdx.x;
    int base = b * SCAN_CHUNK + t * 4;
    int v[4];
#pragma unroll
    for (int k = 0; k < 4; k++)
        v[k] = (base + k < N_NODES) ? g_deg[base + k] : 0;
    int tsum = v[0] + v[1] + v[2] + v[3];
    sums[t] = tsum;
    __syncthreads();
    for (int off = 1; off < 256; off <<= 1) {
        int add = (t >= off) ? sums[t - off] : 0;
        __syncthreads();
        sums[t] += add;
        __syncthreads();
    }
    if (t == 255) g_bsum[b] = sums[255];
    int run = sums[t] - tsum;
#pragma unroll
    for (int k = 0; k < 4; k++) {
        if (base + k < N_NODES) g_rowptr[base + k] = run;
        run += v[k];
    }
}

__global__ void __launch_bounds__(128) scan2_kernel() {
    __shared__ int s[128];
    int t = threadIdx.x;
    int orig = (t < NSCAN_BLOCKS) ? g_bsum[t] : 0;
    s[t] = orig;
    __syncthreads();
    for (int off = 1; off < 128; off <<= 1) {
        int add = (t >= off) ? s[t - off] : 0;
        __syncthreads();
        s[t] += add;
        __syncthreads();
    }
    if (t < NSCAN_BLOCKS) g_bsum[t] = s[t] - orig;
}

__global__ void scan3_kernel() {
    int i = blockIdx.x * blockDim.x + threadIdx.x;
    if (i >= N_NODES) return;
    int rp = g_rowptr[i] + g_bsum[i >> 10];
    g_rowptr[i] = rp;
    g_cursor[i] = rp;
}

// ---------------- CSR fill: group cols by row -------------------------------
__global__ void fill_kernel() {
    int e = blockIdx.x * blockDim.x + threadIdx.x;
    if (e >= N_EDGES) return;
    int r = g_rows[e];
    int pos = atomicAdd(&g_cursor[r], 1);
    g_edst[pos] = g_cols[e];
}

// ---------------- persistent tf32 wmma GEMM + sigmoid -----------------------
// Warp w owns output columns [w*16, w*16+16) for EVERY tile. Its 16 B
// fragments (one per k-step, 64 regs total) are loaded from shared W ONCE
// and live in registers for the whole kernel -> the inner loop is just
// A-fragment load (global, L1-shared across the 8 warps) + convert + mma.
__global__ void __launch_bounds__(256, 2)
gemm_kernel(const float* __restrict__ x, const float* __restrict__ W,
            const float* __restrict__ b) {
    extern __shared__ float dyn[];
    float* smW = dyn;                      // [128][WLD]
    float* smB = dyn + 128 * WLD;          // [16][128]

    const int tid  = threadIdx.x;
    const int warp = tid >> 5;

    for (int i = tid; i < HIDDEN * HIDDEN; i += 256)
        smW[(i >> 7) * WLD + (i & 127)] = wmma::__float_to_tf32(W[i]);
    for (int i = tid; i < 16 * HIDDEN; i += 256)
        smB[i] = b[i & (HIDDEN - 1)];
    __syncthreads();

    // Hoist all B fragments for this warp's column slice into registers.
    wmma::fragment<wmma::matrix_b, 16, 16, 8, wmma::precision::tf32,
                   wmma::col_major> bfr[16];
#pragma unroll
    for (int k = 0; k < 16; k++)
        wmma::load_matrix_sync(bfr[k], smW + (warp * 16) * WLD + k * 8, WLD);

    for (int tile = blockIdx.x; tile < 2 * NTILES; tile += gridDim.x) {
        const int s    = (tile >= NTILES) ? 1 : 0;
        const int t    = tile - s * NTILES;
        const int row0 = t * TILE_ROWS;

        const float* xs = x + ((size_t)s * N_NODES + row0) * HIDDEN;

        wmma::fragment<wmma::accumulator, 16, 16, 8, float> acc;
        wmma::load_matrix_sync(acc, smB + warp * 16, HIDDEN,
                               wmma::mem_row_major);

#pragma unroll
        for (int k = 0; k < 16; k++) {
            wmma::fragment<wmma::matrix_a, 16, 16, 8, wmma::precision::tf32,
                           wmma::row_major> a;
            wmma::load_matrix_sync(a, xs + k * 8, HIDDEN);
#pragma unroll
            for (int q = 0; q < a.num_elements; q++)
                a.x[q] = wmma::__float_to_tf32(a.x[q]);
            wmma::mma_sync(acc, a, bfr[k], acc);
        }

#pragma unroll
        for (int q = 0; q < acc.num_elements; q++) {
            float v = acc.x[q];
            acc.x[q] = 1.0f / (1.0f + __expf(-v));
        }
        float* outp = (s == 0 ? g_S : g_I) + (size_t)row0 * HIDDEN + warp * 16;
        wmma::store_matrix_sync(outp, acc, HIDDEN, wmma::mem_row_major);
    }
}

// ---------------- fp32 I -> bf16 mirror -------------------------------------
// Gathered rows only feed the AI sum; bf16 there costs ~3e-4 rel on AI while
// halving the gather's L2 traffic. dR/dI keep the fp32 I.
__global__ void __launch_bounds__(256)
ibf_kernel() {
    int i = blockIdx.x * blockDim.x + threadIdx.x;   // one per 8 floats
    const int n8 = N_NODES * HIDDEN / 8;
    if (i >= n8) return;
    const float4* src = (const float4*)g_I;
    float4 a = src[2 * i], c = src[2 * i + 1];
    uint4 pk;
    pk.x = bf2_to_u32(__float22bfloat162_rn(make_float2(a.x, a.y)));
    pk.y = bf2_to_u32(__float22bfloat162_rn(make_float2(a.z, a.w)));
    pk.z = bf2_to_u32(__float22bfloat162_rn(make_float2(c.x, c.y)));
    pk.w = bf2_to_u32(__float22bfloat162_rn(make_float2(c.z, c.w)));
    ((uint4*)g_Ibf)[i] = pk;
}

// ---------------- fused CSR gather + epilogue -------------------------------
// One warp per row; lane l owns 4 consecutive features (8 bytes of bf16 on
// the gather side, one float4 on the fp32 side).
__global__ void __launch_bounds__(256)
gather_final_kernel(const float* __restrict__ x, float* __restrict__ out) {
    const int w    = blockIdx.x * 8 + (threadIdx.x >> 5);   // 100000 % 8 == 0
    const int lane = threadIdx.x & 31;

    const int start = g_rowptr[w];
    const int deg   = g_deg[w];
    const uint2* Ib = (const uint2*)g_Ibf;   // 32 uint2 per 128-elem row

    float4 acc = make_float4(0.f, 0.f, 0.f, 0.f);
    int j = 0;
    for (; j + 4 <= deg; j += 4) {
        int c0 = __ldg(g_edst + start + j);
        int c1 = __ldg(g_edst + start + j + 1);
        int c2 = __ldg(g_edst + start + j + 2);
        int c3 = __ldg(g_edst + start + j + 3);
        uint2 u0 = __ldg(Ib + (size_t)c0 * 32 + lane);
        uint2 u1 = __ldg(Ib + (size_t)c1 * 32 + lane);
        uint2 u2 = __ldg(Ib + (size_t)c2 * 32 + lane);
        uint2 u3 = __ldg(Ib + (size_t)c3 * 32 + lane);
#pragma unroll
        for (int q = 0; q < 4; q++) {
            uint2 u = (q == 0) ? u0 : (q == 1) ? u1 : (q == 2) ? u2 : u3;
            float2 lo = u32_to_f2(u.x);
            float2 hi = u32_to_f2(u.y);
            acc.x += lo.x; acc.y += lo.y; acc.z += hi.x; acc.w += hi.y;
        }
    }
    for (; j < deg; j++) {
        int c = __ldg(g_edst + start + j);
        uint2 u = __ldg(Ib + (size_t)c * 32 + lane);
        float2 lo = u32_to_f2(u.x);
        float2 hi = u32_to_f2(u.y);
        acc.x += lo.x; acc.y += lo.y; acc.z += hi.x; acc.w += hi.y;
    }

    float2 bg = __ldg((const float2*)(x + ((size_t)3 * N_NODES + w) * HIDDEN));
    const float beta = bg.x, gamma = bg.y;

    const int idx = w * 32 + lane;
    float4 sv = ((const float4*)g_S)[idx];
    float4 iv = ((const float4*)g_I)[idx];

    float4 dS, dI, dR;
    dS.x = -beta * acc.x * sv.x;  dS.y = -beta * acc.y * sv.y;
    dS.z = -beta * acc.z * sv.z;  dS.w = -beta * acc.w * sv.w;
    dR.x = gamma * iv.x;  dR.y = gamma * iv.y;
    dR.z = gamma * iv.z;  dR.w = gamma * iv.w;
    dI.x = -dS.x - dR.x;  dI.y = -dS.y - dR.y;
    dI.z = -dS.z - dR.z;  dI.w = -dS.w - dR.w;

    const int NQ = N_NODES * 32;
    float4* o = (float4*)out;
    o[idx]          = dS;
    o[NQ + idx]     = dI;
    o[2 * NQ + idx] = dR;
    o[3 * NQ + idx] = make_float4(0.f, 0.f, 0.f, 0.f);
}

// ---------------- launch ----------------------------------------------------
extern "C" void kernel_launch(void* const* d_in, const int* in_sizes, int n_in,
                              void* d_out, int out_size) {
    const float* x    = (const float*)d_in[0];
    const float* W    = (const float*)d_in[1];
    const float* b    = (const float*)d_in[2];
    const void*  rows = d_in[3];
    const void*  cols = d_in[4];
    float* out = (float*)d_out;

    cudaFuncSetAttribute(gemm_kernel,
                         cudaFuncAttributeMaxDynamicSharedMemorySize,
                         GEMM_SMEM);

    detect_kernel<<<1, 1>>>(rows);
    zero_deg_kernel<<<(N_NODES + 255) / 256, 256>>>();
    convert_hist_kernel<<<(N_EDGES + 255) / 256, 256>>>(rows, cols);

    scan1_kernel<<<NSCAN_BLOCKS, 256>>>();
    scan2_kernel<<<1, 128>>>();
    scan3_kernel<<<(N_NODES + 255) / 256, 256>>>();
    fill_kernel<<<(N_EDGES + 255) / 256, 256>>>();

    gemm_kernel<<<GEMM_GRID, 256, GEMM_SMEM>>>(x, W, b);
    ibf_kernel<<<(N_NODES * HIDDEN / 8 + 255) / 256, 256>>>();

    gather_final_kernel<<<N_NODES / 8, 256>>>(x, out);
}